// round 13
// baseline (speedup 1.0000x reference)
#include <cuda_runtime.h>
#include <cuda_fp16.h>
#include <cuda.h>
#include <dlfcn.h>
#include <cstdint>

#define NUM_T 64
#define DIN   4096
#define DOUT  11008
#define KS    4
#define KPER  (DIN / KS)       // 1024
#define KC    64
#define NCHUNK (KPER / KC)     // 16
#define NT    64
#define SSTRIDE 72             // +8 half pad: 144B rows, conflict-free ldmatrix
// smem layout (bytes):
//   [0, 36864)       : 2 f16 stages (X tile 9216 + W tile 9216 each)
//   [36864, 36888)   : 3 mbarriers (pad to 128)
//   [36992, 86144)   : raw W ring, 3 x 16384
#define F16_STAGE_B 18432
#define XW_OFF      9216
#define MBAR_OFF    36864
#define RAW_OFF     36992
#define RAW_STAGE_B 16384
#define SMEM_TOTAL  (RAW_OFF + 3 * RAW_STAGE_B)   // 86144 -> 2 CTAs/SM

// Scratch (allocation-free rule: __device__ globals)
__device__ __align__(256) __half g_xq[NUM_T * DIN];
__device__ __align__(256) float  g_part[KS * NUM_T * DOUT];   // 11.27 MB

// ---------------------------------------------------------------------------
// MXFP4 block constants from amax (integer bit-pattern construction)
// ---------------------------------------------------------------------------
__device__ __forceinline__ void mk_consts(float amax, float& c6s, float& cM,
                                          uint32_t& c2s_bits) {
    if (!(amax > 0.0f)) amax = 1.0f;
    int e  = ((__float_as_int(amax) >> 23) & 0xFF) - 127;
    int se = min(max(e - 2, -127), 127);
    c6s = __int_as_float(((se + 129) << 23) | 0x400000);   // 6 * 2^se
    cM  = __int_as_float((se + 149) << 23);                // 2^(se+22) magic
    c2s_bits = (uint32_t)((se + 128) << 23);               // bits of 2^(se+1)
}

// E2M1 qdq in the t-domain; exactly matches reference (rel_err 0.0 proven).
__device__ __forceinline__ float qdq_fast(float t, float c6s, float cM,
                                          uint32_t c2s_bits) {
    float a = fminf(fabsf(t), c6s);
    uint32_t u = __float_as_uint(a);
    uint32_t r1 = (u + 0x1FFFFFu + ((u >> 22) & 1u)) & 0xFFC00000u;
    float q2 = __fadd_rn(__fadd_rn(a, cM), -cM);
    uint32_t q = (u < c2s_bits) ? __float_as_uint(q2) : r1;
    return __uint_as_float(q | (__float_as_uint(t) & 0x80000000u));
}

// pack two exact f32 values into f16x2 (lo = x, hi = y); conversion exact
__device__ __forceinline__ uint32_t pack_h2(float x, float y) {
    uint32_t r;
    asm("cvt.rn.f16x2.f32 %0, %1, %2;" : "=r"(r) : "f"(y), "f"(x));
    return r;
}

// ---------------------------------------------------------------------------
// x quant-dequant -> f16 (one MXFP block = 8 lanes x float4)
// ---------------------------------------------------------------------------
__global__ void qdq_x_kernel(const float* __restrict__ in) {
    int gtid = blockIdx.x * blockDim.x + threadIdx.x;
    int warp = gtid >> 5;
    int lane = threadIdx.x & 31;
    long base = (long)warp * 128 + (long)lane * 4;
    if (base >= NUM_T * DIN) return;
    float4 v = *reinterpret_cast<const float4*>(in + base);
    float am = fmaxf(fmaxf(fabsf(v.x), fabsf(v.y)), fmaxf(fabsf(v.z), fabsf(v.w)));
    am = fmaxf(am, __shfl_xor_sync(0xffffffffu, am, 1));
    am = fmaxf(am, __shfl_xor_sync(0xffffffffu, am, 2));
    am = fmaxf(am, __shfl_xor_sync(0xffffffffu, am, 4));
    float c6s, cM; uint32_t c2sb;
    mk_consts(am, c6s, cM, c2sb);
    uint2 st;
    st.x = pack_h2(qdq_fast(v.x, c6s, cM, c2sb), qdq_fast(v.y, c6s, cM, c2sb));
    st.y = pack_h2(qdq_fast(v.z, c6s, cM, c2sb), qdq_fast(v.w, c6s, cM, c2sb));
    *reinterpret_cast<uint2*>(&g_xq[base]) = st;
}

// ---------------------------------------------------------------------------
// Fused GEMM (R5 structure) with TMA-loaded raw W (3-deep mbarrier ring).
// ---------------------------------------------------------------------------
#define LDMATRIX_X4(r0, r1, r2, r3, addr)                                        \
    asm volatile("ldmatrix.sync.aligned.m8n8.x4.shared.b16 {%0,%1,%2,%3}, [%4];" \
                 : "=r"(r0), "=r"(r1), "=r"(r2), "=r"(r3) : "r"(addr))

#define MMA16816(c, a0, a1, a2, a3, b0, b1)                                   \
    asm volatile("mma.sync.aligned.m16n8k16.row.col.f32.f16.f16.f32 "         \
                 "{%0,%1,%2,%3}, {%4,%5,%6,%7}, {%8,%9}, {%0,%1,%2,%3};"      \
                 : "+f"(c[0]), "+f"(c[1]), "+f"(c[2]), "+f"(c[3])             \
                 : "r"(a0), "r"(a1), "r"(a2), "r"(a3), "r"(b0), "r"(b1))

__global__ __launch_bounds__(256) void fused_gemm_kernel(
        const __grid_constant__ CUtensorMap tmap) {
    extern __shared__ char smem[];
    __half* smh = reinterpret_cast<__half*>(smem);
    int tid  = threadIdx.x;
    int wid  = tid >> 5;
    int lane = tid & 31;
    int nbase = blockIdx.x * NT;
    int kbase = blockIdx.y * KPER;
    int mrow  = (wid >> 1) * 16;
    int ncol  = (wid & 1) * 32;

    float acc[4][4];
    #pragma unroll
    for (int i = 0; i < 4; i++)
        #pragma unroll
        for (int j = 0; j < 4; j++) acc[i][j] = 0.0f;

    uint32_t smem_u32 = (uint32_t)__cvta_generic_to_shared(smem);
    int q = lane >> 3, li = lane & 7;
    uint32_t a_base = smem_u32 +
        ((mrow + (q & 1) * 8 + li) * SSTRIDE + (q >> 1) * 8) * 2;
    uint32_t b_base = smem_u32 + XW_OFF +
        ((ncol + (q >> 1) * 8 + li) * SSTRIDE + (q & 1) * 8) * 2;

    // W quant map: lane l of warp wid, step i handles 16B unit (l&7)+8*(i&1)
    // of raw row 4*wid + (l>>3) + 32*(i>>1). Conflict-free LDS.128 phases.
    int rowA  = 4 * wid + (lane >> 3);
    int unit0 = lane & 7;
    // X map (R5): 2 uint4 per thread from g_xq (L2-hot)
    int xr0 = tid >> 3,         xc0 = (tid & 7) * 8;
    int xr1 = (tid + 256) >> 3, xc1 = (tid & 7) * 8;
    const __half* xp0 = &g_xq[xr0 * DIN + kbase + xc0];
    const __half* xp1 = &g_xq[xr1 * DIN + kbase + xc1];
    uint4 xv0, xv1;

    // init mbarriers
    if (tid == 0) {
        #pragma unroll
        for (int s = 0; s < 3; s++)
            asm volatile("mbarrier.init.shared.b64 [%0], 1;"
                         :: "r"(smem_u32 + MBAR_OFF + s * 8) : "memory");
    }
    __syncthreads();

    auto tma_issue = [&](int c) {
        uint32_t bar = smem_u32 + MBAR_OFF + (c % 3) * 8;
        uint32_t dst = smem_u32 + RAW_OFF + (c % 3) * RAW_STAGE_B;
        asm volatile("mbarrier.arrive.expect_tx.shared.b64 _, [%0], %1;"
                     :: "r"(bar), "r"(16384) : "memory");
        asm volatile(
            "cp.async.bulk.tensor.2d.shared::cta.global.tile.mbarrier::complete_tx::bytes "
            "[%0], [%1, {%2, %3}], [%4];"
            :: "r"(dst), "l"(&tmap), "r"(kbase + c * KC), "r"(nbase), "r"(bar)
            : "memory");
    };
    auto wait_full = [&](int c) {
        uint32_t bar = smem_u32 + MBAR_OFF + (c % 3) * 8;
        uint32_t ph  = (uint32_t)((c / 3) & 1);
        asm volatile(
            "{\n\t.reg .pred P;\n"
            "W%=:\n\tmbarrier.try_wait.parity.acquire.cta.shared::cta.b64 P, [%0], %1;\n\t"
            "@P bra D%=;\n\tbra W%=;\nD%=:\n\t}"
            :: "r"(bar), "r"(ph) : "memory");
    };

    // stage chunk c: X from prefetched regs; W from raw ring -> qdq -> f16 tile
    auto stagec = [&](int c) {
        int s = c & 1;
        __half* Xs = smh + s * (F16_STAGE_B / 2);
        *reinterpret_cast<uint4*>(&Xs[xr0 * SSTRIDE + xc0]) = xv0;
        *reinterpret_cast<uint4*>(&Xs[xr1 * SSTRIDE + xc1]) = xv1;
        uint32_t raw   = smem_u32 + RAW_OFF + (c % 3) * RAW_STAGE_B;
        uint32_t wbase = smem_u32 + s * F16_STAGE_B + XW_OFF;
        #pragma unroll
        for (int i = 0; i < 4; i++) {
            int row  = rowA + 32 * (i >> 1);
            int unit = unit0 + 8 * (i & 1);
            float vx, vy, vz, vw;
            asm volatile("ld.shared.v4.f32 {%0,%1,%2,%3}, [%4];"
                         : "=f"(vx), "=f"(vy), "=f"(vz), "=f"(vw)
                         : "r"(raw + row * 256 + unit * 16));
            float am = fmaxf(fmaxf(fabsf(vx), fabsf(vy)), fmaxf(fabsf(vz), fabsf(vw)));
            am = fmaxf(am, __shfl_xor_sync(0xffffffffu, am, 1));
            am = fmaxf(am, __shfl_xor_sync(0xffffffffu, am, 2));
            am = fmaxf(am, __shfl_xor_sync(0xffffffffu, am, 4));  // 8 lanes = 32-block
            float c6s, cM; uint32_t c2sb;
            mk_consts(am, c6s, cM, c2sb);
            uint32_t p0 = pack_h2(qdq_fast(vx, c6s, cM, c2sb), qdq_fast(vy, c6s, cM, c2sb));
            uint32_t p1 = pack_h2(qdq_fast(vz, c6s, cM, c2sb), qdq_fast(vw, c6s, cM, c2sb));
            asm volatile("st.shared.v2.b32 [%0], {%1,%2};"
                         :: "r"(wbase + row * (SSTRIDE * 2) + unit * 8),
                            "r"(p0), "r"(p1) : "memory");
        }
    };

    // -------- prologue: TMA 0,1,2 in flight; stage chunk 0 --------
    if (tid == 0) { tma_issue(0); tma_issue(1); tma_issue(2); }
    xv0 = *reinterpret_cast<const uint4*>(xp0);
    xv1 = *reinterpret_cast<const uint4*>(xp1);
    wait_full(0);
    stagec(0);
    xv0 = *reinterpret_cast<const uint4*>(xp0 + KC);
    xv1 = *reinterpret_cast<const uint4*>(xp1 + KC);
    __syncthreads();

    // -------- main loop: one barrier per chunk --------
    #pragma unroll 1
    for (int c = 0; c < NCHUNK; c++) {
        if (tid == 0 && c + 3 < NCHUNK)
            tma_issue(c + 3);            // slot (c%3): reads finished in iter c-1
        if (c + 1 < NCHUNK) {
            wait_full(c + 1);
            stagec(c + 1);
            if (c + 2 < NCHUNK) {
                xv0 = *reinterpret_cast<const uint4*>(xp0 + (c + 2) * KC);
                xv1 = *reinterpret_cast<const uint4*>(xp1 + (c + 2) * KC);
            }
        }
        uint32_t off = (c & 1) * F16_STAGE_B;
        #pragma unroll
        for (int ks = 0; ks < 4; ks++) {
            uint32_t a0, a1, a2, a3;
            LDMATRIX_X4(a0, a1, a2, a3, a_base + off + ks * 32);
            #pragma unroll
            for (int nb = 0; nb < 2; nb++) {
                uint32_t b0, b1, b2, b3;
                LDMATRIX_X4(b0, b1, b2, b3,
                            b_base + off + nb * (16 * SSTRIDE * 2) + ks * 32);
                MMA16816(acc[nb * 2 + 0], a0, a1, a2, a3, b0, b1);
                MMA16816(acc[nb * 2 + 1], a0, a1, a2, a3, b2, b3);
            }
        }
        __syncthreads();
    }

    // epilogue: fp32 partials (R5 layout)
    float* pb = g_part + (size_t)blockIdx.y * NUM_T * DOUT;
    int tg = lane >> 2, tig = lane & 3;
    #pragma unroll
    for (int nf = 0; nf < 4; nf++) {
        int col = nbase + ncol + nf * 8 + tig * 2;
        int r0  = mrow + tg;
        *reinterpret_cast<float2*>(&pb[(size_t)r0 * DOUT + col]) =
            make_float2(acc[nf][0], acc[nf][1]);
        *reinterpret_cast<float2*>(&pb[(size_t)(r0 + 8) * DOUT + col]) =
            make_float2(acc[nf][2], acc[nf][3]);
    }
}

// ---------------------------------------------------------------------------
// Reduce K-splits + bias qdq. 1 thread = 1 float4 of output.
// ---------------------------------------------------------------------------
__global__ void reduce_bias_kernel(const float* __restrict__ bias, float* __restrict__ out) {
    int t  = blockIdx.x * blockDim.x + threadIdx.x;
    int m  = t / (DOUT / 4);
    int o  = (t % (DOUT / 4)) * 4;

    float4 b4 = *reinterpret_cast<const float4*>(bias + o);
    float am = fmaxf(fmaxf(fabsf(b4.x), fabsf(b4.y)), fmaxf(fabsf(b4.z), fabsf(b4.w)));
    am = fmaxf(am, __shfl_xor_sync(0xffffffffu, am, 1));
    am = fmaxf(am, __shfl_xor_sync(0xffffffffu, am, 2));
    am = fmaxf(am, __shfl_xor_sync(0xffffffffu, am, 4));
    float c6s, cM; uint32_t c2sb;
    mk_consts(am, c6s, cM, c2sb);

    size_t idx = (size_t)m * DOUT + o;
    const size_t ps = (size_t)NUM_T * DOUT;
    float4 r;
    r.x = qdq_fast(b4.x, c6s, cM, c2sb);
    r.y = qdq_fast(b4.y, c6s, cM, c2sb);
    r.z = qdq_fast(b4.z, c6s, cM, c2sb);
    r.w = qdq_fast(b4.w, c6s, cM, c2sb);
    #pragma unroll
    for (int s = 0; s < KS; s++) {
        float4 p = *reinterpret_cast<const float4*>(g_part + s * ps + idx);
        r.x += p.x; r.y += p.y; r.z += p.z; r.w += p.w;
    }
    *reinterpret_cast<float4*>(out + idx) = r;
}

// ---------------------------------------------------------------------------
typedef CUresult (*PFN_encode)(CUtensorMap*, CUtensorMapDataType, cuuint32_t,
                               void*, const cuuint64_t*, const cuuint64_t*,
                               const cuuint32_t*, const cuuint32_t*,
                               CUtensorMapInterleave, CUtensorMapSwizzle,
                               CUtensorMapL2promotion, CUtensorMapFloatOOBfill);

static PFN_encode get_encoder() {
    static PFN_encode fn = nullptr;
    if (!fn) {
        void* h = dlopen("libcuda.so.1", RTLD_NOW | RTLD_GLOBAL);
        if (!h) h = dlopen("libcuda.so", RTLD_NOW | RTLD_GLOBAL);
        if (h) fn = (PFN_encode)dlsym(h, "cuTensorMapEncodeTiled");
    }
    return fn;
}

extern "C" void kernel_launch(void* const* d_in, const int* in_sizes, int n_in,
                              void* d_out, int out_size) {
    const float* x = nullptr;
    const float* wgt = nullptr;
    const float* bias = nullptr;
    for (int i = 0; i < n_in; i++) {
        if (in_sizes[i] == NUM_T * DIN)     x    = (const float*)d_in[i];
        else if (in_sizes[i] == DOUT * DIN) wgt  = (const float*)d_in[i];
        else if (in_sizes[i] == DOUT)       bias = (const float*)d_in[i];
    }
    float* out = (float*)d_out;

    // Build 2D tensor map for W [DOUT rows, DIN cols], f32, box 64x64, no swizzle
    CUtensorMap tmap;
    {
        PFN_encode enc = get_encoder();
        cuuint64_t dims[2]    = {(cuuint64_t)DIN, (cuuint64_t)DOUT};
        cuuint64_t strides[1] = {(cuuint64_t)DIN * sizeof(float)};
        cuuint32_t box[2]     = {KC, NT};
        cuuint32_t estr[2]    = {1, 1};
        enc(&tmap, CU_TENSOR_MAP_DATA_TYPE_FLOAT32, 2, (void*)wgt,
            dims, strides, box, estr,
            CU_TENSOR_MAP_INTERLEAVE_NONE, CU_TENSOR_MAP_SWIZZLE_NONE,
            CU_TENSOR_MAP_L2_PROMOTION_L2_128B,
            CU_TENSOR_MAP_FLOAT_OOB_FILL_NONE);
    }

    cudaFuncSetAttribute(fused_gemm_kernel,
                         cudaFuncAttributeMaxDynamicSharedMemorySize, SMEM_TOTAL);

    qdq_x_kernel<<<NUM_T * DIN / 4 / 128, 128>>>(x);
    fused_gemm_kernel<<<dim3(DOUT / NT, KS), 256, SMEM_TOTAL>>>(tmap);
    reduce_bias_kernel<<<(NUM_T * DOUT / 4) / 256, 256>>>(bias, out);
    (void)out_size;
}

// round 14
// speedup vs baseline: 2.1121x; 2.1121x over previous
#include <cuda_runtime.h>
#include <cuda_fp16.h>
#include <cstdint>

#define NUM_T 64
#define DIN   4096
#define DOUT  11008
#define KS    4
#define KPER  (DIN / KS)     // 1024
#define KC    64
#define NCHUNK (KPER / KC)   // 16
#define NT    64
#define SSTRIDE 72           // +8 half pad: row stride 144B, conflict-free ldmatrix
#define STAGE_BYTES (NUM_T * SSTRIDE * 2)   // 9216

// Scratch (allocation-free rule: __device__ globals)
__device__ __align__(256) __half g_xq[NUM_T * DIN];
__device__ __align__(256) float  g_part[KS * NUM_T * DOUT];   // 11.27 MB

// ---------------------------------------------------------------------------
// MXFP4 block constants from amax (integer bit-pattern construction):
//   se  = clip(floor(log2 amax) - 2, -127, 127)     (scale = 2^se, never built)
//   c6s = 6 * 2^se ; cM = 2^(se+22) (magic) ; c2s_bits = bits(2^(se+1))
// ---------------------------------------------------------------------------
__device__ __forceinline__ void mk_consts(float amax, float& c6s, float& cM,
                                          uint32_t& c2s_bits) {
    if (!(amax > 0.0f)) amax = 1.0f;
    int e  = ((__float_as_int(amax) >> 23) & 0xFF) - 127;
    int se = min(max(e - 2, -127), 127);
    c6s = __int_as_float(((se + 129) << 23) | 0x400000);   // 1.5 * 2^(se+2)
    cM  = __int_as_float((se + 149) << 23);                // 2^(se+22)
    c2s_bits = (uint32_t)((se + 128) << 23);               // bits of 2^(se+1)
}

// E2M1 qdq in the t-domain (no per-element scale mults). Matches reference
// exactly: clip to 6*scale, RNE on E2M1 grid incl. 0.5*scale subnormal step.
__device__ __forceinline__ float qdq_fast(float t, float c6s, float cM,
                                          uint32_t c2s_bits) {
    float a = fminf(fabsf(t), c6s);
    uint32_t u = __float_as_uint(a);
    uint32_t r1 = (u + 0x1FFFFFu + ((u >> 22) & 1u)) & 0xFFC00000u;  // RNE, 1 mant bit
    float q2 = __fadd_rn(__fadd_rn(a, cM), -cM);                     // RNE to scale/2 grid
    uint32_t q = (u < c2s_bits) ? __float_as_uint(q2) : r1;
    return __uint_as_float(q | (__float_as_uint(t) & 0x80000000u));
}

// ---------------------------------------------------------------------------
// x quant-dequant -> f16. One MXFP block (32 floats) = 8 lanes x float4.
// ---------------------------------------------------------------------------
__global__ void qdq_x_kernel(const float* __restrict__ in) {
    int gtid = blockIdx.x * blockDim.x + threadIdx.x;
    int warp = gtid >> 5;
    int lane = threadIdx.x & 31;
    long base = (long)warp * 128 + (long)lane * 4;
    if (base >= NUM_T * DIN) return;
    float4 v = *reinterpret_cast<const float4*>(in + base);
    float am = fmaxf(fmaxf(fabsf(v.x), fabsf(v.y)), fmaxf(fabsf(v.z), fabsf(v.w)));
    am = fmaxf(am, __shfl_xor_sync(0xffffffffu, am, 1));
    am = fmaxf(am, __shfl_xor_sync(0xffffffffu, am, 2));
    am = fmaxf(am, __shfl_xor_sync(0xffffffffu, am, 4));
    float c6s, cM; uint32_t c2sb;
    mk_consts(am, c6s, cM, c2sb);
    __half2 h0 = __floats2half2_rn(qdq_fast(v.x, c6s, cM, c2sb),
                                   qdq_fast(v.y, c6s, cM, c2sb));
    __half2 h1 = __floats2half2_rn(qdq_fast(v.z, c6s, cM, c2sb),
                                   qdq_fast(v.w, c6s, cM, c2sb));
    uint2 st;
    st.x = *reinterpret_cast<uint32_t*>(&h0);
    st.y = *reinterpret_cast<uint32_t*>(&h1);
    *reinterpret_cast<uint2*>(&g_xq[base]) = st;
}

// ---------------------------------------------------------------------------
// Fused GEMM, double-buffered (R5), MMA-first issue order per chunk.
// ---------------------------------------------------------------------------
#define LDMATRIX_X4(r0, r1, r2, r3, addr)                                        \
    asm volatile("ldmatrix.sync.aligned.m8n8.x4.shared.b16 {%0,%1,%2,%3}, [%4];" \
                 : "=r"(r0), "=r"(r1), "=r"(r2), "=r"(r3) : "r"(addr))

#define MMA16816(c, a0, a1, a2, a3, b0, b1)                                   \
    asm volatile("mma.sync.aligned.m16n8k16.row.col.f32.f16.f16.f32 "         \
                 "{%0,%1,%2,%3}, {%4,%5,%6,%7}, {%8,%9}, {%0,%1,%2,%3};"      \
                 : "+f"(c[0]), "+f"(c[1]), "+f"(c[2]), "+f"(c[3])             \
                 : "r"(a0), "r"(a1), "r"(a2), "r"(a3), "r"(b0), "r"(b1))

__global__ __launch_bounds__(256) void fused_gemm_kernel(const float* __restrict__ W) {
    __shared__ __half Xs[2][NUM_T][SSTRIDE];
    __shared__ __half Ws[2][NT][SSTRIDE];

    int tid  = threadIdx.x;
    int w    = tid >> 5;
    int lane = tid & 31;
    int nbase = blockIdx.x * NT;
    int kbase = blockIdx.y * KPER;
    int mrow  = (w >> 1) * 16;
    int ncol  = (w & 1) * 32;

    float acc[4][4];
    #pragma unroll
    for (int i = 0; i < 4; i++)
        #pragma unroll
        for (int j = 0; j < 4; j++) acc[i][j] = 0.0f;

    int q = lane >> 3, li = lane & 7;
    uint32_t a_base0 = (uint32_t)__cvta_generic_to_shared(
        &Xs[0][mrow + (q & 1) * 8 + li][(q >> 1) * 8]);
    uint32_t b_base0 = (uint32_t)__cvta_generic_to_shared(
        &Ws[0][ncol + (q >> 1) * 8 + li][(q & 1) * 8]);

    // W load map: 4 threads per row, 16 consecutive floats each (half a 32-block)
    int wrow = tid >> 2;
    int wk   = (tid & 3) << 4;
    const float* wp = W + (size_t)(nbase + wrow) * DIN + kbase + wk;
    // X load map: 2 uint4 per thread
    int c0 = tid, c1 = tid + 256;
    int xr0 = c0 >> 3, xc0 = (c0 & 7) * 8;
    int xr1 = c1 >> 3, xc1 = (c1 & 7) * 8;
    const __half* xp0 = &g_xq[xr0 * DIN + kbase + xc0];
    const __half* xp1 = &g_xq[xr1 * DIN + kbase + xc1];

    float4 wv[4];
    uint4  xv[2];

    auto stage = [&](int s) {
        *reinterpret_cast<uint4*>(&Xs[s][xr0][xc0]) = xv[0];
        *reinterpret_cast<uint4*>(&Xs[s][xr1][xc1]) = xv[1];
        float am = 0.0f;
        #pragma unroll
        for (int j = 0; j < 4; j++)
            am = fmaxf(am, fmaxf(fmaxf(fabsf(wv[j].x), fabsf(wv[j].y)),
                                 fmaxf(fabsf(wv[j].z), fabsf(wv[j].w))));
        am = fmaxf(am, __shfl_xor_sync(0xffffffffu, am, 1));  // pair -> 32-block amax
        float c6s, cM; uint32_t c2sb;
        mk_consts(am, c6s, cM, c2sb);
        uint32_t qq[8];
        #pragma unroll
        for (int j = 0; j < 4; j++) {
            __half2 h0 = __floats2half2_rn(qdq_fast(wv[j].x, c6s, cM, c2sb),
                                           qdq_fast(wv[j].y, c6s, cM, c2sb));
            __half2 h1 = __floats2half2_rn(qdq_fast(wv[j].z, c6s, cM, c2sb),
                                           qdq_fast(wv[j].w, c6s, cM, c2sb));
            qq[2 * j]     = *reinterpret_cast<uint32_t*>(&h0);
            qq[2 * j + 1] = *reinterpret_cast<uint32_t*>(&h1);
        }
        *reinterpret_cast<uint4*>(&Ws[s][wrow][wk])     = make_uint4(qq[0], qq[1], qq[2], qq[3]);
        *reinterpret_cast<uint4*>(&Ws[s][wrow][wk + 8]) = make_uint4(qq[4], qq[5], qq[6], qq[7]);
    };

    // -------- prologue: load chunk0, quant -> stage0, load chunk1 --------
    #pragma unroll
    for (int j = 0; j < 4; j++)
        wv[j] = reinterpret_cast<const float4*>(wp)[j];
    xv[0] = *reinterpret_cast<const uint4*>(xp0);
    xv[1] = *reinterpret_cast<const uint4*>(xp1);
    stage(0);
    #pragma unroll
    for (int j = 0; j < 4; j++)
        wv[j] = reinterpret_cast<const float4*>(wp + KC)[j];
    xv[0] = *reinterpret_cast<const uint4*>(xp0 + KC);
    xv[1] = *reinterpret_cast<const uint4*>(xp1 + KC);
    __syncthreads();

    // -------- main loop: MMA first, then stage/prefetch, one barrier --------
    #pragma unroll 1
    for (int c16 = 0; c16 < NCHUNK; c16++) {
        // MMA over staged chunk c16 issues immediately after the barrier;
        // its latency retires under the quant work below.
        uint32_t a_s = a_base0 + (c16 & 1) * STAGE_BYTES;
        uint32_t b_s = b_base0 + (c16 & 1) * STAGE_BYTES;
        #pragma unroll
        for (int ks = 0; ks < 4; ks++) {
            uint32_t a0, a1, a2, a3;
            LDMATRIX_X4(a0, a1, a2, a3, a_s + ks * 32);
            #pragma unroll
            for (int nb = 0; nb < 2; nb++) {
                uint32_t b0, b1, b2, b3;
                LDMATRIX_X4(b0, b1, b2, b3, b_s + nb * 16 * SSTRIDE * 2 + ks * 32);
                MMA16816(acc[nb * 2 + 0], a0, a1, a2, a3, b0, b1);
                MMA16816(acc[nb * 2 + 1], a0, a1, a2, a3, b2, b3);
            }
        }
        // quant chunk c16+1 (in regs) into the other stage buffer
        if (c16 + 1 < NCHUNK)
            stage((c16 + 1) & 1);
        // prefetch chunk c16+2 into regs
        if (c16 + 2 < NCHUNK) {
            int kc = (c16 + 2) * KC;
            #pragma unroll
            for (int j = 0; j < 4; j++)
                wv[j] = reinterpret_cast<const float4*>(wp + kc)[j];
            xv[0] = *reinterpret_cast<const uint4*>(xp0 + kc);
            xv[1] = *reinterpret_cast<const uint4*>(xp1 + kc);
        }
        __syncthreads();
    }

    // epilogue: fp32 partials
    float* pb = g_part + (size_t)blockIdx.y * NUM_T * DOUT;
    int tg = lane >> 2, tig = lane & 3;
    #pragma unroll
    for (int nf = 0; nf < 4; nf++) {
        int col = nbase + ncol + nf * 8 + tig * 2;
        int r0  = mrow + tg;
        pb[(size_t)r0 * DOUT + col]           = acc[nf][0];
        pb[(size_t)r0 * DOUT + col + 1]       = acc[nf][1];
        pb[(size_t)(r0 + 8) * DOUT + col]     = acc[nf][2];
        pb[(size_t)(r0 + 8) * DOUT + col + 1] = acc[nf][3];
    }
}

// ---------------------------------------------------------------------------
// Reduce K-splits + bias qdq (inline). 1 thread = 1 float4 of output.
// ---------------------------------------------------------------------------
__global__ void reduce_bias_kernel(const float* __restrict__ bias, float* __restrict__ out) {
    int t  = blockIdx.x * blockDim.x + threadIdx.x;
    int m  = t / (DOUT / 4);
    int o  = (t % (DOUT / 4)) * 4;

    float4 b4 = *reinterpret_cast<const float4*>(bias + o);
    float am = fmaxf(fmaxf(fabsf(b4.x), fabsf(b4.y)), fmaxf(fabsf(b4.z), fabsf(b4.w)));
    am = fmaxf(am, __shfl_xor_sync(0xffffffffu, am, 1));
    am = fmaxf(am, __shfl_xor_sync(0xffffffffu, am, 2));
    am = fmaxf(am, __shfl_xor_sync(0xffffffffu, am, 4));
    float c6s, cM; uint32_t c2sb;
    mk_consts(am, c6s, cM, c2sb);
    float b0 = qdq_fast(b4.x, c6s, cM, c2sb);
    float b1 = qdq_fast(b4.y, c6s, cM, c2sb);
    float b2 = qdq_fast(b4.z, c6s, cM, c2sb);
    float b3 = qdq_fast(b4.w, c6s, cM, c2sb);

    size_t idx = (size_t)m * DOUT + o;
    const size_t ps = (size_t)NUM_T * DOUT;
    float4 s0 = *reinterpret_cast<const float4*>(g_part + idx);
    float4 s1 = *reinterpret_cast<const float4*>(g_part + ps + idx);
    float4 s2 = *reinterpret_cast<const float4*>(g_part + 2 * ps + idx);
    float4 s3 = *reinterpret_cast<const float4*>(g_part + 3 * ps + idx);

    float4 r;
    r.x = (s0.x + s1.x) + (s2.x + s3.x) + b0;
    r.y = (s0.y + s1.y) + (s2.y + s3.y) + b1;
    r.z = (s0.z + s1.z) + (s2.z + s3.z) + b2;
    r.w = (s0.w + s1.w) + (s2.w + s3.w) + b3;
    *reinterpret_cast<float4*>(out + idx) = r;
}

// ---------------------------------------------------------------------------
extern "C" void kernel_launch(void* const* d_in, const int* in_sizes, int n_in,
                              void* d_out, int out_size) {
    const float* x = nullptr;
    const float* wgt = nullptr;
    const float* bias = nullptr;
    for (int i = 0; i < n_in; i++) {
        if (in_sizes[i] == NUM_T * DIN)     x    = (const float*)d_in[i];
        else if (in_sizes[i] == DOUT * DIN) wgt  = (const float*)d_in[i];
        else if (in_sizes[i] == DOUT)       bias = (const float*)d_in[i];
    }
    float* out = (float*)d_out;

    qdq_x_kernel<<<NUM_T * DIN / 4 / 128, 128>>>(x);
    fused_gemm_kernel<<<dim3(DOUT / NT, KS), 256>>>(wgt);
    reduce_bias_kernel<<<(NUM_T * DOUT / 4) / 256, 256>>>(bias, out);
    (void)out_size;
}